// round 4
// baseline (speedup 1.0000x reference)
#include <cuda_runtime.h>
#include <cuda_bf16.h>
#include <cstdint>

#define B_DIM 4096
#define DIN   4096
#define DBN   32768
#define KSEL  64
#define CAND  96

// ---- GEMM tiling: CTA 128(M) x 256(N), KC=32, 4-stage cp.async, 8 warps (2x4), warp 64x64 ----
#define TM 128
#define TN 256
#define KC 32
#define NT (DIN / KC)             // 128
#define A_STAGE 8192              // 128 rows x 64B
#define B_STAGE 16384             // 256 rows x 64B
#define SB_OFF  (4 * A_STAGE)     // 32768
#define SMEM_GEMM (SB_OFF + 4 * B_STAGE)  // 98304

// ---------------- scratch (device globals: allocation-free) ----------------
__device__ __nv_bfloat16 g_xb[(size_t)B_DIM * DIN];   // 32 MB
__device__ __nv_bfloat16 g_wb[(size_t)DBN * DIN];     // 256 MB
__device__ __nv_bfloat16 g_a1[(size_t)B_DIM * DBN];   // 256 MB (bf16 scores)
__device__ int           g_cand[(size_t)B_DIM * CAND];

__device__ __forceinline__ unsigned sw_off(int row, int c) {
    // rows are 64B (4 x 16B chunks); XOR pairs of rows across chunks: conflict-free
    return (unsigned)(row * 64 + ((c ^ ((row >> 1) & 3)) << 4));
}

// ---------------- K0: fp32 -> bf16 convert ----------------
__global__ void convert_kernel(const float* __restrict__ x, const float* __restrict__ w) {
    size_t nx = (size_t)B_DIM * DIN / 4;
    size_t nw = (size_t)DBN * DIN / 4;
    size_t stride = (size_t)gridDim.x * blockDim.x;
    for (size_t t = (size_t)blockIdx.x * blockDim.x + threadIdx.x; t < nx + nw; t += stride) {
        if (t < nx) {
            float4 v = ((const float4*)x)[t];
            __nv_bfloat162* o = reinterpret_cast<__nv_bfloat162*>(g_xb);
            o[2 * t]     = __floats2bfloat162_rn(v.x, v.y);
            o[2 * t + 1] = __floats2bfloat162_rn(v.z, v.w);
        } else {
            size_t u = t - nx;
            float4 v = ((const float4*)w)[u];
            __nv_bfloat162* o = reinterpret_cast<__nv_bfloat162*>(g_wb);
            o[2 * u]     = __floats2bfloat162_rn(v.x, v.y);
            o[2 * u + 1] = __floats2bfloat162_rn(v.z, v.w);
        }
    }
}

// ---------------- K1: bf16 encode GEMM  a1 = bf16(x @ W^T + b_enc) ----------------
__global__ void __launch_bounds__(256, 1) encode_gemm(const float* __restrict__ b_enc) {
    extern __shared__ __align__(128) char smem[];
    const unsigned smem_base = (unsigned)__cvta_generic_to_shared(smem);

    const int tid = threadIdx.x;
    const int wid = tid >> 5, lane = tid & 31;
    const int wm = wid >> 2, wn = wid & 3;     // 2 x 4 warp grid, warp tile 64x64

    const int m0 = blockIdx.x * TM;            // x fastest: share B tile within a wave
    const int n0 = blockIdx.y * TN;

    const __nv_bfloat16* gA0 = g_xb + (size_t)m0 * DIN;
    const __nv_bfloat16* gB0 = g_wb + (size_t)n0 * DIN;

    float acc[4][8][4];
#pragma unroll
    for (int i = 0; i < 4; i++)
#pragma unroll
        for (int j = 0; j < 8; j++)
#pragma unroll
            for (int r = 0; r < 4; r++) acc[i][j][r] = 0.f;

    // one K-chunk: A 512 16B-chunks, B 1024 -> 6 per thread
#define LOAD_CHUNK(kc, s)                                                                \
    do {                                                                                 \
        unsigned aBase = smem_base + (s) * A_STAGE;                                      \
        unsigned bBase = smem_base + SB_OFF + (s) * B_STAGE;                             \
        _Pragma("unroll")                                                                \
        for (int _j = 0; _j < 6; _j++) {                                                 \
            int idx = tid + 256 * _j;                                                    \
            if (idx < 512) {                                                             \
                int r = idx >> 2, c = idx & 3;                                           \
                unsigned dst = aBase + sw_off(r, c);                                     \
                const void* src = gA0 + (size_t)r * DIN + (kc) * KC + c * 8;             \
                asm volatile("cp.async.cg.shared.global [%0],[%1],16;\n"                 \
                             :: "r"(dst), "l"(src));                                     \
            } else {                                                                     \
                int k2 = idx - 512;                                                      \
                int r = k2 >> 2, c = k2 & 3;                                             \
                unsigned dst = bBase + sw_off(r, c);                                     \
                const void* src = gB0 + (size_t)r * DIN + (kc) * KC + c * 8;             \
                asm volatile("cp.async.cg.shared.global [%0],[%1],16;\n"                 \
                             :: "r"(dst), "l"(src));                                     \
            }                                                                            \
        }                                                                                \
        asm volatile("cp.async.commit_group;\n");                                       \
    } while (0)

    LOAD_CHUNK(0, 0);
    LOAD_CHUNK(1, 1);
    LOAD_CHUNK(2, 2);

    for (int i = 0; i < NT; i++) {
        const int buf = i & 3;
        if (i + 3 < NT) {
            asm volatile("cp.async.wait_group 2;\n");
            __syncthreads();                       // stage i visible; stage (i-1)%4 free
            LOAD_CHUNK(i + 3, (i + 3) & 3);
        } else {
            asm volatile("cp.async.wait_group 0;\n");
            __syncthreads();
        }

        const unsigned aS = smem_base + buf * A_STAGE;
        const unsigned bS = smem_base + SB_OFF + buf * B_STAGE;
#pragma unroll
        for (int ks = 0; ks < 2; ks++) {
            unsigned a[4][4];
#pragma unroll
            for (int i2 = 0; i2 < 4; i2++) {
                int row = wm * 64 + i2 * 16 + (lane & 7) + ((lane >> 3) & 1) * 8;
                int c   = ks * 2 + (lane >> 4);
                unsigned addr = aS + sw_off(row, c);
                asm volatile("ldmatrix.sync.aligned.m8n8.x4.shared.b16 {%0,%1,%2,%3},[%4];\n"
                             : "=r"(a[i2][0]), "=r"(a[i2][1]), "=r"(a[i2][2]), "=r"(a[i2][3])
                             : "r"(addr));
            }
            unsigned b[8][2];
#pragma unroll
            for (int jj = 0; jj < 4; jj++) {
                int row = wn * 64 + jj * 16 + ((lane >> 4) & 1) * 8 + (lane & 7);
                int c   = ks * 2 + ((lane >> 3) & 1);
                unsigned addr = bS + sw_off(row, c);
                unsigned r0, r1, r2, r3;
                asm volatile("ldmatrix.sync.aligned.m8n8.x4.shared.b16 {%0,%1,%2,%3},[%4];\n"
                             : "=r"(r0), "=r"(r1), "=r"(r2), "=r"(r3)
                             : "r"(addr));
                b[2 * jj][0] = r0;     b[2 * jj][1] = r1;
                b[2 * jj + 1][0] = r2; b[2 * jj + 1][1] = r3;
            }
#pragma unroll
            for (int i2 = 0; i2 < 4; i2++)
#pragma unroll
                for (int j = 0; j < 8; j++) {
                    asm volatile(
                        "mma.sync.aligned.m16n8k16.row.col.f32.bf16.bf16.f32 "
                        "{%0,%1,%2,%3},{%4,%5,%6,%7},{%8,%9},{%0,%1,%2,%3};\n"
                        : "+f"(acc[i2][j][0]), "+f"(acc[i2][j][1]),
                          "+f"(acc[i2][j][2]), "+f"(acc[i2][j][3])
                        : "r"(a[i2][0]), "r"(a[i2][1]), "r"(a[i2][2]), "r"(a[i2][3]),
                          "r"(b[j][0]), "r"(b[j][1]));
                }
        }
        __syncthreads();
    }
#undef LOAD_CHUNK

    // epilogue: +b_enc, bf16 store
    const int mrow = m0 + wm * 64;
    const int ncol = n0 + wn * 64;
#pragma unroll
    for (int i2 = 0; i2 < 4; i2++) {
#pragma unroll
        for (int j = 0; j < 8; j++) {
            int r  = mrow + i2 * 16 + (lane >> 2);
            int cc = ncol + j * 8 + (lane & 3) * 2;
            float be0 = __ldg(&b_enc[cc]);
            float be1 = __ldg(&b_enc[cc + 1]);
            __nv_bfloat162 v0 = __floats2bfloat162_rn(acc[i2][j][0] + be0, acc[i2][j][1] + be1);
            __nv_bfloat162 v1 = __floats2bfloat162_rn(acc[i2][j][2] + be0, acc[i2][j][3] + be1);
            *reinterpret_cast<__nv_bfloat162*>(&g_a1[(size_t)r * DBN + cc])       = v0;
            *reinterpret_cast<__nv_bfloat162*>(&g_a1[(size_t)(r + 8) * DBN + cc]) = v1;
        }
    }
}

// ---------------- K2: single-histogram top-CAND candidate select over bf16 a1 ----------------
__device__ __forceinline__ unsigned fkey16(unsigned u) {
    u &= 0xFFFFu;
    return (u & 0x8000u) ? ((~u) & 0xFFFFu) : (u | 0x8000u);
}

__global__ void __launch_bounds__(256) topk_kernel() {
    const int row = blockIdx.x;
    const int tid = threadIdx.x;

    __shared__ unsigned hist[4096];
    __shared__ unsigned part[256];
    __shared__ unsigned s_tbin;
    __shared__ int lcnt;
    __shared__ unsigned short keyl[512];
    __shared__ int idxl[512];

    for (int i = tid; i < 4096; i += 256) hist[i] = 0;
    if (tid == 0) lcnt = 0;
    __syncthreads();

    const uint4* p4 = reinterpret_cast<const uint4*>(g_a1 + (size_t)row * DBN);
#pragma unroll 4
    for (int j = 0; j < 16; j++) {
        uint4 v = p4[tid + 256 * j];
        unsigned w[4] = {v.x, v.y, v.z, v.w};
#pragma unroll
        for (int q = 0; q < 4; q++) {
            atomicAdd(&hist[fkey16(w[q]) >> 4], 1u);
            atomicAdd(&hist[fkey16(w[q] >> 16) >> 4], 1u);
        }
    }
    __syncthreads();

    unsigned ps = 0;
#pragma unroll
    for (int b = 0; b < 16; b++) ps += hist[tid * 16 + b];
    part[tid] = ps;
    __syncthreads();

    if (tid == 0) {
        unsigned cum = 0;
        int g = 255;
        for (; g > 0; g--) {
            if (cum + part[g] >= CAND) break;
            cum += part[g];
        }
        int b = g * 16 + 15;
        for (; b > 0; b--) {
            unsigned c = hist[b];
            if (cum + c >= CAND) break;
            cum += c;
        }
        s_tbin = (unsigned)b;
    }
    __syncthreads();
    const unsigned tb = s_tbin;

#pragma unroll 4
    for (int j = 0; j < 16; j++) {
        int vi = tid + 256 * j;
        uint4 v = p4[vi];
        unsigned w[4] = {v.x, v.y, v.z, v.w};
        int base = vi * 8;
#pragma unroll
        for (int q = 0; q < 4; q++) {
            unsigned k0 = fkey16(w[q]);
            unsigned k1 = fkey16(w[q] >> 16);
            if ((k0 >> 4) >= tb) {
                int pos = atomicAdd(&lcnt, 1);
                if (pos < 512) { keyl[pos] = (unsigned short)k0; idxl[pos] = base + 2 * q; }
            }
            if ((k1 >> 4) >= tb) {
                int pos = atomicAdd(&lcnt, 1);
                if (pos < 512) { keyl[pos] = (unsigned short)k1; idxl[pos] = base + 2 * q + 1; }
            }
        }
    }
    __syncthreads();

    const int L = lcnt < 512 ? lcnt : 512;
    for (int e = tid; e < L; e += 256) {
        const unsigned kv = keyl[e];
        const int ii = idxl[e];
        int rank = 0;
        for (int j2 = 0; j2 < L; j2++) {
            unsigned kj = keyl[j2];
            if (kj > kv || (kj == kv && idxl[j2] < ii)) rank++;
        }
        if (rank < CAND) g_cand[(size_t)row * CAND + rank] = ii;
    }
}

// ---------------- K3: exact rescore (Kahan + fp64 reduce) + top-64 + fused decode ----------------
__global__ void __launch_bounds__(256) rescore_decode_kernel(
    const float* __restrict__ x, const float* __restrict__ W,
    const float* __restrict__ b_enc, const float* __restrict__ b_dec,
    float* __restrict__ out) {
    const int row = blockIdx.x;
    const int tid = threadIdx.x;
    const int wid = tid >> 5, lane = tid & 31;

    __shared__ float  sx[DIN];
    __shared__ double sval[CAND];
    __shared__ int    scan_[CAND];
    __shared__ float  sv[KSEL];
    __shared__ int    si[KSEL];
    __shared__ int    cnt;

    const float4* xg  = reinterpret_cast<const float4*>(x + (size_t)row * DIN);
    float4*       sx4 = reinterpret_cast<float4*>(sx);
    for (int i = tid; i < DIN / 4; i += 256) sx4[i] = xg[i];
    if (tid == 0) cnt = 0;
    __syncthreads();

    for (int c = wid; c < CAND; c += 8) {
        const int idx = g_cand[(size_t)row * CAND + c];
        const float4* wv = reinterpret_cast<const float4*>(W + (size_t)idx * DIN);
        float s = 0.f, comp = 0.f;
#define ACC(aa, bb)                                      \
        {                                                \
            float p = (aa) * (bb);                       \
            float e = __fmaf_rn((aa), (bb), -p);         \
            float t = s + p;                             \
            comp += (s - t) + p;                         \
            s = t;                                       \
            comp += e;                                   \
        }
        for (int i = lane; i < DIN / 4; i += 32) {
            float4 w = wv[i], xx = sx4[i];
            ACC(w.x, xx.x) ACC(w.y, xx.y) ACC(w.z, xx.z) ACC(w.w, xx.w)
        }
#undef ACC
        double d = (double)s + (double)comp;
#pragma unroll
        for (int o = 16; o; o >>= 1) d += __shfl_xor_sync(0xFFFFFFFFu, d, o);
        if (lane == 0) { sval[c] = d + (double)b_enc[idx]; scan_[c] = idx; }
    }
    __syncthreads();

    if (tid < CAND) {
        const double v = sval[tid];
        const int   ii = scan_[tid];
        int greater = 0;
        for (int j = 0; j < CAND; j++) {
            double u = sval[j];
            if (u > v || (u == v && scan_[j] < ii)) greater++;
        }
        if (greater < KSEL) {
            int slot = atomicAdd(&cnt, 1);
            sv[slot] = (float)v;
            si[slot] = ii;
        }
    }
    __syncthreads();

    // decode: W rows L2-hot from the rescore gather
    const float4* bd = reinterpret_cast<const float4*>(b_dec);
    float4 acc[4];
#pragma unroll
    for (int s = 0; s < 4; s++) acc[s] = bd[tid + s * 256];

    for (int j = 0; j < KSEL; j++) {
        const float v = sv[j];
        const float4* wr = reinterpret_cast<const float4*>(W + (size_t)si[j] * DIN);
#pragma unroll
        for (int s = 0; s < 4; s++) {
            float4 w = wr[tid + s * 256];
            acc[s].x += v * w.x; acc[s].y += v * w.y;
            acc[s].z += v * w.z; acc[s].w += v * w.w;
        }
    }
    float4* o = reinterpret_cast<float4*>(out + (size_t)row * DIN);
#pragma unroll
    for (int s = 0; s < 4; s++) o[tid + s * 256] = acc[s];
}

// ---------------- launch ----------------
extern "C" void kernel_launch(void* const* d_in, const int* in_sizes, int n_in,
                              void* d_out, int out_size) {
    const float* x     = (const float*)d_in[0];
    const float* W     = (const float*)d_in[1];
    const float* b_enc = (const float*)d_in[2];
    const float* b_dec = (const float*)d_in[3];
    float* out = (float*)d_out;

    cudaFuncSetAttribute(encode_gemm,
                         cudaFuncAttributeMaxDynamicSharedMemorySize, SMEM_GEMM);

    convert_kernel<<<2368, 256>>>(x, W);

    dim3 g1(B_DIM / TM, DBN / TN);   // (32, 128), x fastest over M
    encode_gemm<<<g1, 256, SMEM_GEMM>>>(b_enc);

    topk_kernel<<<B_DIM, 256>>>();
    rescore_decode_kernel<<<B_DIM, 256>>>(x, W, b_enc, b_dec, out);
}

// round 5
// speedup vs baseline: 1.1292x; 1.1292x over previous
#include <cuda_runtime.h>
#include <cuda_bf16.h>
#include <cstdint>

#define B_DIM 4096
#define DIN   4096
#define DBN   32768
#define KSEL  64
#define CAND  80

// ---------------- scratch (device globals: allocation-free) ----------------
__device__ __nv_bfloat16 g_xb[(size_t)B_DIM * DIN];   // 32 MB
__device__ __nv_bfloat16 g_wb[(size_t)DBN * DIN];     // 256 MB
__device__ __nv_bfloat16 g_a1[(size_t)B_DIM * DBN];   // 256 MB (bf16 scores)
__device__ int           g_cand[(size_t)B_DIM * CAND];

// ---------------- K0: fp32 -> bf16 convert ----------------
__global__ void convert_kernel(const float* __restrict__ x, const float* __restrict__ w) {
    size_t nx = (size_t)B_DIM * DIN / 4;
    size_t nw = (size_t)DBN * DIN / 4;
    size_t stride = (size_t)gridDim.x * blockDim.x;
    for (size_t t = (size_t)blockIdx.x * blockDim.x + threadIdx.x; t < nx + nw; t += stride) {
        if (t < nx) {
            float4 v = ((const float4*)x)[t];
            __nv_bfloat162* o = reinterpret_cast<__nv_bfloat162*>(g_xb);
            o[2 * t]     = __floats2bfloat162_rn(v.x, v.y);
            o[2 * t + 1] = __floats2bfloat162_rn(v.z, v.w);
        } else {
            size_t u = t - nx;
            float4 v = ((const float4*)w)[u];
            __nv_bfloat162* o = reinterpret_cast<__nv_bfloat162*>(g_wb);
            o[2 * u]     = __floats2bfloat162_rn(v.x, v.y);
            o[2 * u + 1] = __floats2bfloat162_rn(v.z, v.w);
        }
    }
}

// ---------------- K1: bf16 encode GEMM (a1 = bf16(x @ W^T + b_enc)) ----------------
// EXACT R2 structure (proven ~2.3-2.4 ms): block tile 128x128, K-tile 32, 2-stage
// cp.async, 256 threads (8 warps: 2x4 -> warp tile 64x32). Only the epilogue differs:
// bf16 store (halves the a1 store stream).

__device__ __forceinline__ unsigned sw_off(int row, int c) {
    // 16B-chunk XOR swizzle: conflict-free for cp.async stores and ldmatrix
    return (unsigned)(row * 64 + ((c ^ ((row >> 1) & 3)) << 4));
}

__global__ void __launch_bounds__(256) encode_gemm(const float* __restrict__ b_enc) {
    const int m0 = blockIdx.x * 128;   // batch tile (x-fastest: CTAs sharing W tile run together)
    const int n0 = blockIdx.y * 128;   // latent tile

    __shared__ __align__(16) __nv_bfloat16 sA[2][128 * 32];
    __shared__ __align__(16) __nv_bfloat16 sB[2][128 * 32];

    const int tid = threadIdx.x;
    const int wid = tid >> 5, lane = tid & 31;
    const int wm = wid >> 2, wn = wid & 3;      // warp grid 2 x 4

    unsigned sA_base = (unsigned)__cvta_generic_to_shared(&sA[0][0]);
    unsigned sB_base = (unsigned)__cvta_generic_to_shared(&sB[0][0]);

    const __nv_bfloat16* gA = g_xb + (size_t)m0 * DIN;
    const __nv_bfloat16* gB = g_wb + (size_t)n0 * DIN;

    float acc[4][4][4];
#pragma unroll
    for (int i = 0; i < 4; i++)
#pragma unroll
        for (int j = 0; j < 4; j++)
#pragma unroll
            for (int r = 0; r < 4; r++) acc[i][j][r] = 0.f;

    // cp.async tile loader: 512 chunks of 16B per tile, 2 per thread
#define LOAD_TILE(buf, kt)                                                              \
    do {                                                                                \
        _Pragma("unroll")                                                               \
        for (int _i = 0; _i < 2; _i++) {                                                \
            int cid = tid + 256 * _i;                                                   \
            int row = cid >> 2, c = cid & 3;                                            \
            unsigned off = sw_off(row, c);                                              \
            const __nv_bfloat16* srcA = gA + (size_t)row * DIN + (kt) + c * 8;          \
            const __nv_bfloat16* srcB = gB + (size_t)row * DIN + (kt) + c * 8;          \
            unsigned da = sA_base + (buf) * 8192u + off;                                \
            unsigned db = sB_base + (buf) * 8192u + off;                                \
            asm volatile("cp.async.cg.shared.global [%0],[%1],16;\n" ::"r"(da), "l"(srcA)); \
            asm volatile("cp.async.cg.shared.global [%0],[%1],16;\n" ::"r"(db), "l"(srcB)); \
        }                                                                               \
        asm volatile("cp.async.commit_group;\n");                                      \
    } while (0)

    LOAD_TILE(0, 0);
    const int NT = DIN / 32;  // 128
    for (int t = 0; t < NT; t++) {
        if (t + 1 < NT) {
            LOAD_TILE((t + 1) & 1, (t + 1) * 32);
            asm volatile("cp.async.wait_group 1;\n");
        } else {
            asm volatile("cp.async.wait_group 0;\n");
        }
        __syncthreads();
        const int buf = t & 1;
#pragma unroll
        for (int ks = 0; ks < 2; ks++) {
            unsigned a[4][4];
#pragma unroll
            for (int i = 0; i < 4; i++) {
                int row = wm * 64 + i * 16 + (lane & 7) + ((lane >> 3) & 1) * 8;
                int c   = ks * 2 + (lane >> 4);
                unsigned addr = sA_base + buf * 8192u + sw_off(row, c);
                asm volatile("ldmatrix.sync.aligned.m8n8.x4.shared.b16 {%0,%1,%2,%3},[%4];\n"
                             : "=r"(a[i][0]), "=r"(a[i][1]), "=r"(a[i][2]), "=r"(a[i][3])
                             : "r"(addr));
            }
            unsigned b[4][2];
#pragma unroll
            for (int jj = 0; jj < 2; jj++) {
                int row = wn * 32 + jj * 16 + ((lane >> 4) & 1) * 8 + (lane & 7);
                int c   = ks * 2 + ((lane >> 3) & 1);
                unsigned addr = sB_base + buf * 8192u + sw_off(row, c);
                unsigned r0, r1, r2, r3;
                asm volatile("ldmatrix.sync.aligned.m8n8.x4.shared.b16 {%0,%1,%2,%3},[%4];\n"
                             : "=r"(r0), "=r"(r1), "=r"(r2), "=r"(r3)
                             : "r"(addr));
                b[2 * jj][0] = r0; b[2 * jj][1] = r1;
                b[2 * jj + 1][0] = r2; b[2 * jj + 1][1] = r3;
            }
#pragma unroll
            for (int i = 0; i < 4; i++)
#pragma unroll
                for (int j = 0; j < 4; j++) {
                    asm volatile(
                        "mma.sync.aligned.m16n8k16.row.col.f32.bf16.bf16.f32 "
                        "{%0,%1,%2,%3},{%4,%5,%6,%7},{%8,%9},{%0,%1,%2,%3};\n"
                        : "+f"(acc[i][j][0]), "+f"(acc[i][j][1]),
                          "+f"(acc[i][j][2]), "+f"(acc[i][j][3])
                        : "r"(a[i][0]), "r"(a[i][1]), "r"(a[i][2]), "r"(a[i][3]),
                          "r"(b[j][0]), "r"(b[j][1]));
                }
        }
        __syncthreads();
    }
#undef LOAD_TILE

    // epilogue: + b_enc, store bf16 a1
    const int mrow = m0 + wm * 64;
    const int ncol = n0 + wn * 32;
#pragma unroll
    for (int i = 0; i < 4; i++) {
#pragma unroll
        for (int j = 0; j < 4; j++) {
            int r  = mrow + i * 16 + (lane >> 2);
            int cc = ncol + j * 8 + (lane & 3) * 2;
            float be0 = __ldg(&b_enc[cc]);
            float be1 = __ldg(&b_enc[cc + 1]);
            __nv_bfloat162 v0 = __floats2bfloat162_rn(acc[i][j][0] + be0, acc[i][j][1] + be1);
            __nv_bfloat162 v1 = __floats2bfloat162_rn(acc[i][j][2] + be0, acc[i][j][3] + be1);
            *reinterpret_cast<__nv_bfloat162*>(&g_a1[(size_t)r * DBN + cc])       = v0;
            *reinterpret_cast<__nv_bfloat162*>(&g_a1[(size_t)(r + 8) * DBN + cc]) = v1;
        }
    }
}

// ---------------- K2: single-histogram top-CAND candidate select over bf16 a1 ----------------
__device__ __forceinline__ unsigned fkey16(unsigned u) {
    u &= 0xFFFFu;
    return (u & 0x8000u) ? ((~u) & 0xFFFFu) : (u | 0x8000u);
}

__global__ void __launch_bounds__(256) topk_kernel() {
    const int row = blockIdx.x;
    const int tid = threadIdx.x;

    __shared__ unsigned hist[4096];
    __shared__ unsigned part[256];
    __shared__ unsigned s_tbin;
    __shared__ int lcnt;
    __shared__ unsigned short keyl[512];
    __shared__ int idxl[512];

    for (int i = tid; i < 4096; i += 256) hist[i] = 0;
    if (tid == 0) lcnt = 0;
    __syncthreads();

    const uint4* p4 = reinterpret_cast<const uint4*>(g_a1 + (size_t)row * DBN);
#pragma unroll 4
    for (int j = 0; j < 16; j++) {
        uint4 v = p4[tid + 256 * j];
        unsigned w[4] = {v.x, v.y, v.z, v.w};
#pragma unroll
        for (int q = 0; q < 4; q++) {
            atomicAdd(&hist[fkey16(w[q]) >> 4], 1u);
            atomicAdd(&hist[fkey16(w[q] >> 16) >> 4], 1u);
        }
    }
    __syncthreads();

    unsigned ps = 0;
#pragma unroll
    for (int b = 0; b < 16; b++) ps += hist[tid * 16 + b];
    part[tid] = ps;
    __syncthreads();

    if (tid == 0) {
        unsigned cum = 0;
        int g = 255;
        for (; g > 0; g--) {
            if (cum + part[g] >= CAND) break;
            cum += part[g];
        }
        int b = g * 16 + 15;
        for (; b > 0; b--) {
            unsigned c = hist[b];
            if (cum + c >= CAND) break;
            cum += c;
        }
        s_tbin = (unsigned)b;
    }
    __syncthreads();
    const unsigned tb = s_tbin;

#pragma unroll 4
    for (int j = 0; j < 16; j++) {
        int vi = tid + 256 * j;
        uint4 v = p4[vi];
        unsigned w[4] = {v.x, v.y, v.z, v.w};
        int base = vi * 8;
#pragma unroll
        for (int q = 0; q < 4; q++) {
            unsigned k0 = fkey16(w[q]);
            unsigned k1 = fkey16(w[q] >> 16);
            if ((k0 >> 4) >= tb) {
                int pos = atomicAdd(&lcnt, 1);
                if (pos < 512) { keyl[pos] = (unsigned short)k0; idxl[pos] = base + 2 * q; }
            }
            if ((k1 >> 4) >= tb) {
                int pos = atomicAdd(&lcnt, 1);
                if (pos < 512) { keyl[pos] = (unsigned short)k1; idxl[pos] = base + 2 * q + 1; }
            }
        }
    }
    __syncthreads();

    const int L = lcnt < 512 ? lcnt : 512;
    for (int e = tid; e < L; e += 256) {
        const unsigned kv = keyl[e];
        const int ii = idxl[e];
        int rank = 0;
        for (int j2 = 0; j2 < L; j2++) {
            unsigned kj = keyl[j2];
            if (kj > kv || (kj == kv && idxl[j2] < ii)) rank++;
        }
        if (rank < CAND) g_cand[(size_t)row * CAND + rank] = ii;
    }
}

// ---------------- K3: exact rescore (Kahan + fp64 reduce) + top-64 + fused decode ----------------
__global__ void __launch_bounds__(256) rescore_decode_kernel(
    const float* __restrict__ x, const float* __restrict__ W,
    const float* __restrict__ b_enc, const float* __restrict__ b_dec,
    float* __restrict__ out) {
    const int row = blockIdx.x;
    const int tid = threadIdx.x;
    const int wid = tid >> 5, lane = tid & 31;

    __shared__ float  sx[DIN];
    __shared__ double sval[CAND];
    __shared__ int    scan_[CAND];
    __shared__ float  sv[KSEL];
    __shared__ int    si[KSEL];
    __shared__ int    cnt;

    const float4* xg  = reinterpret_cast<const float4*>(x + (size_t)row * DIN);
    float4*       sx4 = reinterpret_cast<float4*>(sx);
    for (int i = tid; i < DIN / 4; i += 256) sx4[i] = xg[i];
    if (tid == 0) cnt = 0;
    __syncthreads();

    for (int c = wid; c < CAND; c += 8) {
        const int idx = g_cand[(size_t)row * CAND + c];
        const float4* wv = reinterpret_cast<const float4*>(W + (size_t)idx * DIN);
        float s = 0.f, comp = 0.f;
#define ACC(aa, bb)                                      \
        {                                                \
            float p = (aa) * (bb);                       \
            float e = __fmaf_rn((aa), (bb), -p);         \
            float t = s + p;                             \
            comp += (s - t) + p;                         \
            s = t;                                       \
            comp += e;                                   \
        }
        for (int i = lane; i < DIN / 4; i += 32) {
            float4 w = wv[i], xx = sx4[i];
            ACC(w.x, xx.x) ACC(w.y, xx.y) ACC(w.z, xx.z) ACC(w.w, xx.w)
        }
#undef ACC
        double d = (double)s + (double)comp;
#pragma unroll
        for (int o = 16; o; o >>= 1) d += __shfl_xor_sync(0xFFFFFFFFu, d, o);
        if (lane == 0) { sval[c] = d + (double)b_enc[idx]; scan_[c] = idx; }
    }
    __syncthreads();

    if (tid < CAND) {
        const double v = sval[tid];
        const int   ii = scan_[tid];
        int greater = 0;
        for (int j = 0; j < CAND; j++) {
            double u = sval[j];
            if (u > v || (u == v && scan_[j] < ii)) greater++;
        }
        if (greater < KSEL) {
            int slot = atomicAdd(&cnt, 1);
            sv[slot] = (float)v;
            si[slot] = ii;
        }
    }
    __syncthreads();

    // decode: W rows L2-hot from the rescore gather
    const float4* bd = reinterpret_cast<const float4*>(b_dec);
    float4 acc[4];
#pragma unroll
    for (int s = 0; s < 4; s++) acc[s] = bd[tid + s * 256];

    for (int j = 0; j < KSEL; j++) {
        const float v = sv[j];
        const float4* wr = reinterpret_cast<const float4*>(W + (size_t)si[j] * DIN);
#pragma unroll
        for (int s = 0; s < 4; s++) {
            float4 w = wr[tid + s * 256];
            acc[s].x += v * w.x; acc[s].y += v * w.y;
            acc[s].z += v * w.z; acc[s].w += v * w.w;
        }
    }
    float4* o = reinterpret_cast<float4*>(out + (size_t)row * DIN);
#pragma unroll
    for (int s = 0; s < 4; s++) o[tid + s * 256] = acc[s];
}

// ---------------- launch ----------------
extern "C" void kernel_launch(void* const* d_in, const int* in_sizes, int n_in,
                              void* d_out, int out_size) {
    const float* x     = (const float*)d_in[0];
    const float* W     = (const float*)d_in[1];
    const float* b_enc = (const float*)d_in[2];
    const float* b_dec = (const float*)d_in[3];
    float* out = (float*)d_out;

    convert_kernel<<<2368, 256>>>(x, W);

    dim3 g1(B_DIM / 128, DBN / 128);  // x = batch tiles (fast), y = latent tiles
    encode_gemm<<<g1, 256>>>(b_enc);

    topk_kernel<<<B_DIM, 256>>>();
    rescore_decode_kernel<<<B_DIM, 256>>>(x, W, b_enc, b_dec, out);
}